// round 5
// baseline (speedup 1.0000x reference)
#include <cuda_runtime.h>
#include <cuda_fp16.h>
#include <cstdint>

// DigitCapsules dynamic routing, GB300 sm_103a
// B=256, C=10, I=1152, DI=8, DO=16, 3 routing iterations.
//
// u_hat = W@x materialized once in fp16 (fp32 compute, one rounding): 94.4 MB.
// route_kernel: one block per batch element, all 3 iterations fused, vacc in
// warp registers (warp = class). Iterations process tiles in GROUPS of 4 with
// one barrier per group (MLP=8 loads in flight, 18 barriers/block instead of 72).

#define BSZ  256
#define CCL  10
#define ICAP 1152
#define DOV  16
#define DIV  8
#define NG   9            // groups per pass
#define GT   4            // tiles per group (32 i each) -> 9*4*32 = 1152

__device__ __align__(256) __half g_uhat[(size_t)BSZ * CCL * ICAP * DOV]; // 94.4 MB

static __device__ __forceinline__ unsigned int pack_h2(float a, float b) {
    __half2 h = __floats2half2_rn(a, b);
    return *reinterpret_cast<unsigned int*>(&h);
}

// ---------------------------------------------------------------------------
// K_uhat: u_hat[b,c,i,do] = sum_k W[c,i,0,do,k] * x[b,i,k]   (fp32 -> fp16)
// grid = I (block per input capsule), 256 threads = b.
// ---------------------------------------------------------------------------
__global__ __launch_bounds__(256) void uhat_kernel(
    const float* __restrict__ x, const float* __restrict__ W)
{
    const int i = blockIdx.x;
    const int b = threadIdx.x;

    __shared__ float4 Ws[CCL * DOV * 2];   // W[c,i,:,:] rows: 5120 B

    for (int f = threadIdx.x; f < CCL * DOV * 2; f += 256) {
        int c = f >> 5, rem = f & 31, d = rem >> 1, h = rem & 1;
        Ws[f] = *reinterpret_cast<const float4*>(
            W + ((((size_t)c * ICAP + i) * DOV) + d) * DIV + h * 4);
    }

    const float* xp = x + (size_t)b * (ICAP * DIV) + (size_t)i * DIV;
    const float4 x0 = *reinterpret_cast<const float4*>(xp);
    const float4 x1 = *reinterpret_cast<const float4*>(xp + 4);

    __syncthreads();

    __half* up = g_uhat + (size_t)b * (CCL * ICAP * DOV) + (size_t)i * DOV;

    #pragma unroll
    for (int c = 0; c < CCL; c++) {
        float r[DOV];
        #pragma unroll
        for (int d = 0; d < DOV; d++) {
            float4 w0 = Ws[c * 32 + d * 2];
            float4 w1 = Ws[c * 32 + d * 2 + 1];
            float v = w0.x * x0.x;
            v = fmaf(w0.y, x0.y, v); v = fmaf(w0.z, x0.z, v); v = fmaf(w0.w, x0.w, v);
            v = fmaf(w1.x, x1.x, v); v = fmaf(w1.y, x1.y, v);
            v = fmaf(w1.z, x1.z, v); v = fmaf(w1.w, x1.w, v);
            r[d] = v;
        }
        uint4 q0, q1;
        q0.x = pack_h2(r[0],  r[1]);  q0.y = pack_h2(r[2],  r[3]);
        q0.z = pack_h2(r[4],  r[5]);  q0.w = pack_h2(r[6],  r[7]);
        q1.x = pack_h2(r[8],  r[9]);  q1.y = pack_h2(r[10], r[11]);
        q1.z = pack_h2(r[12], r[13]); q1.w = pack_h2(r[14], r[15]);
        __half* o = up + (size_t)c * (ICAP * DOV);
        *reinterpret_cast<uint4*>(o)     = q0;   // 32 B per lane = full sector
        *reinterpret_cast<uint4*>(o + 8) = q1;
    }
}

// unpack one packed tile row (2x uint4 of half2) into 16 floats
static __device__ __forceinline__ void unpack16(const uint4& a, const uint4& b,
                                                float* __restrict__ u) {
    const __half2* ha = reinterpret_cast<const __half2*>(&a);
    const __half2* hb = reinterpret_cast<const __half2*>(&b);
    #pragma unroll
    for (int q = 0; q < 4; q++) {
        float2 f = __half22float2(ha[q]);
        u[q * 2] = f.x; u[q * 2 + 1] = f.y;
    }
    #pragma unroll
    for (int q = 0; q < 4; q++) {
        float2 f = __half22float2(hb[q]);
        u[8 + q * 2] = f.x; u[8 + q * 2 + 1] = f.y;
    }
}

// dot of packed tile with vr[16]
static __device__ __forceinline__ float dot16(const uint4& a, const uint4& b,
                                              const float* __restrict__ vr) {
    float u[DOV];
    unpack16(a, b, u);
    float s = u[0] * vr[0];
    #pragma unroll
    for (int j = 1; j < DOV; j++) s = fmaf(u[j], vr[j], s);
    return s;
}

// fma-accumulate w * packed tile into sac[16]
static __device__ __forceinline__ void acc16(const uint4& a, const uint4& b,
                                             float w, float* __restrict__ sac) {
    float u[DOV];
    unpack16(a, b, u);
    #pragma unroll
    for (int j = 0; j < DOV; j++) sac[j] = fmaf(w, u[j], sac[j]);
}

// ---------------------------------------------------------------------------
// route_kernel: all 3 routing iterations for one batch element.
// grid = B, 320 threads: warp = class c, lane ii = i-slot.
// Tiles processed in groups of 4 (one barrier per group in iters 1-2).
// ---------------------------------------------------------------------------
__global__ __launch_bounds__(320, 2) void route_kernel(float* __restrict__ out)
{
    const int b  = blockIdx.x;
    const int c  = threadIdx.x >> 5;
    const int ii = threadIdx.x & 31;

    __shared__ float e_s[2][GT][CCL][33];   // 10560 B, double-buffered

    const __half* ub = g_uhat + ((size_t)b * CCL + c) * (size_t)ICAP * DOV;

    float vr[DOV];
    #pragma unroll
    for (int j = 0; j < DOV; j++) vr[j] = 0.0f;

    float sac[DOV];

    // ---------------- iteration 0: uniform weights 0.1, no barriers
    #pragma unroll
    for (int j = 0; j < DOV; j++) sac[j] = 0.0f;
    for (int g = 0; g < NG; g++) {
        const __half* tb = ub + (size_t)(g * GT * 32 + ii) * DOV;
        uint4 A[GT][2];
        #pragma unroll
        for (int k = 0; k < GT; k++) {
            const uint4* q = reinterpret_cast<const uint4*>(tb + (size_t)k * 32 * DOV);
            A[k][0] = q[0]; A[k][1] = q[1];
        }
        #pragma unroll
        for (int k = 0; k < GT; k++) acc16(A[k][0], A[k][1], 0.1f, sac);
    }
    #pragma unroll
    for (int off = 16; off > 0; off >>= 1)
        #pragma unroll
        for (int j = 0; j < DOV; j++)
            sac[j] += __shfl_xor_sync(0xffffffffu, sac[j], off);
    {
        float sq = 0.0f;
        #pragma unroll
        for (int j = 0; j < DOV; j++) sq = fmaf(sac[j], sac[j], sq);
        float scale = __fdividef(sqrtf(sq), 1.0f + sq);
        #pragma unroll
        for (int j = 0; j < DOV; j++) vr[j] = sac[j] * scale;
    }

    // ---------------- iterations 1 and 2
    #pragma unroll 1
    for (int t = 1; t < 3; t++) {
        #pragma unroll
        for (int j = 0; j < DOV; j++) sac[j] = 0.0f;

        for (int g = 0; g < NG; g++) {
            const __half* tb = ub + (size_t)(g * GT * 32 + ii) * DOV;
            uint4 A[GT][2];
            #pragma unroll
            for (int k = 0; k < GT; k++) {
                const uint4* q = reinterpret_cast<const uint4*>(tb + (size_t)k * 32 * DOV);
                A[k][0] = q[0]; A[k][1] = q[1];
            }

            const int p = g & 1;
            // logits + exp for the 4 tiles (|logit| bounded ~35: exp safe fp32)
            #pragma unroll
            for (int k = 0; k < GT; k++) {
                float a = dot16(A[k][0], A[k][1], vr);
                e_s[p][k][c][ii] = __expf(a);
            }
            __syncthreads();

            #pragma unroll
            for (int k = 0; k < GT; k++) {
                float Z = e_s[p][k][0][ii];
                #pragma unroll
                for (int cc = 1; cc < CCL; cc++) Z += e_s[p][k][cc][ii];
                float w = __fdividef(e_s[p][k][c][ii], Z);
                acc16(A[k][0], A[k][1], w, sac);
            }
        }

        #pragma unroll
        for (int off = 16; off > 0; off >>= 1)
            #pragma unroll
            for (int j = 0; j < DOV; j++)
                sac[j] += __shfl_xor_sync(0xffffffffu, sac[j], off);

        float sq = 0.0f;
        #pragma unroll
        for (int j = 0; j < DOV; j++) sq = fmaf(sac[j], sac[j], sq);
        float scale = __fdividef(sqrtf(sq), 1.0f + sq);

        if (t == 2) {
            if (ii == 0) {
                float4* op = reinterpret_cast<float4*>(
                    out + ((size_t)b * CCL + c) * DOV);
                op[0] = make_float4(sac[0]*scale,  sac[1]*scale,  sac[2]*scale,  sac[3]*scale);
                op[1] = make_float4(sac[4]*scale,  sac[5]*scale,  sac[6]*scale,  sac[7]*scale);
                op[2] = make_float4(sac[8]*scale,  sac[9]*scale,  sac[10]*scale, sac[11]*scale);
                op[3] = make_float4(sac[12]*scale, sac[13]*scale, sac[14]*scale, sac[15]*scale);
            }
        } else {
            #pragma unroll
            for (int j = 0; j < DOV; j++) vr[j] += sac[j] * scale;
        }
    }
}

// ---------------------------------------------------------------------------
extern "C" void kernel_launch(void* const* d_in, const int* in_sizes, int n_in,
                              void* d_out, int out_size)
{
    const float* x = (const float*)d_in[0];
    const float* W = (const float*)d_in[1];
    if (in_sizes[0] == CCL * ICAP * DOV * DIV) {  // defensively identify by size
        const float* t = x; x = W; W = t;
    }
    float* out = (float*)d_out;

    uhat_kernel<<<ICAP, 256>>>(x, W);
    route_kernel<<<BSZ, 320>>>(out);
}